// round 9
// baseline (speedup 1.0000x reference)
#include <cuda_runtime.h>
#include <float.h>
#include <math.h>

// Problem constants
#define Bn   4
#define Qn   4
#define Fn   20
#define OBJn 20
#define Dn   4096
#define Mn   1000
#define ROWn (OBJn * Dn)          // 81920 floats per (frame|mem) row
#define BFn  (Bn * Fn)            // 80
#define KSPLIT 8
#define MPAD 2048
#define FILLBLKS 1184             // ~148 SMs x 8 blocks

static const size_t RPN = (size_t)Qn * Bn * Fn * ROWn;   // 26,214,400 elems per big output

// ---------------- device scratch ----------------
__device__ float g_mem_mp[2 * Mn * Dn];          // 32.8 MB: normalized maxpooled mem rows
__device__ float g_rmaxn[BFn * Dn];              // normalized maxpooled R rows
__device__ float g_invnorm[BFn * OBJn];          // per-region inverse norms
__device__ float g_partial[KSPLIT * BFn * MPAD]; // k-split partial dots
__device__ int   g_sim[2 * BFn];                 // sim1 (0..79), sim2 (80..159)
__device__ int   g_high[16], g_low[16];          // indexed by b*4+q

// ---------------- helpers ----------------
__device__ __forceinline__ float block_reduce_sum(float v) {
    __shared__ float sh[32];
    __shared__ float res;
    int lane = threadIdx.x & 31, w = threadIdx.x >> 5;
#pragma unroll
    for (int o = 16; o; o >>= 1) v += __shfl_down_sync(0xffffffffu, v, o);
    __syncthreads();
    if (!lane) sh[w] = v;
    __syncthreads();
    if (w == 0) {
        float x = (lane < (int)(blockDim.x >> 5)) ? sh[lane] : 0.f;
#pragma unroll
        for (int o = 16; o; o >>= 1) x += __shfl_down_sync(0xffffffffu, x, o);
        if (!lane) res = x;
    }
    __syncthreads();
    return res;
}

__device__ __forceinline__ float4 fmax4(float4 a, float4 b) {
    a.x = fmaxf(a.x, b.x); a.y = fmaxf(a.y, b.y);
    a.z = fmaxf(a.z, b.z); a.w = fmaxf(a.w, b.w);
    return a;
}

__device__ __forceinline__ float4 ldcs4(const float4* p) {
    return __ldcs(p);
}

// ---------------- K_prep: heterogeneous grid -----------------------------------------
// blocks [0,2000): mem max-pool+norm   [2000,2080): R stats   2080: frame selection
__global__ __launch_bounds__(256) void k_prep(const float* __restrict__ mem1,
                                              const float* __restrict__ mem2,
                                              const float* __restrict__ inp,
                                              const float* __restrict__ qr,
                                              const int* __restrict__ rnd) {
    int blk = blockIdx.x;
    if (blk < 2 * Mn) {
        // ---- mem_mp (streaming; __ldcs keeps single-use data out of L2) ----
        const float* src = (blk >= Mn) ? (mem2 + (size_t)(blk - Mn) * ROWn)
                                       : (mem1 + (size_t)blk * ROWn);
        float4 mx[4];
#pragma unroll
        for (int i = 0; i < 4; i++) mx[i] = make_float4(-FLT_MAX, -FLT_MAX, -FLT_MAX, -FLT_MAX);
        for (int o = 0; o < OBJn; o++) {
            const float4* p = (const float4*)(src + (size_t)o * Dn);
#pragma unroll
            for (int i = 0; i < 4; i++) mx[i] = fmax4(mx[i], ldcs4(p + threadIdx.x + i * 256));
        }
        float s = 0.f;
#pragma unroll
        for (int i = 0; i < 4; i++)
            s += mx[i].x * mx[i].x + mx[i].y * mx[i].y + mx[i].z * mx[i].z + mx[i].w * mx[i].w;
        s = block_reduce_sum(s);
        float inv = 1.f / fmaxf(sqrtf(s), 1e-12f);
        float4* out = (float4*)(g_mem_mp + (size_t)blk * Dn);
#pragma unroll
        for (int i = 0; i < 4; i++) {
            float4 v = mx[i];
            v.x *= inv; v.y *= inv; v.z *= inv; v.w *= inv;
            out[threadIdx.x + i * 256] = v;
        }
    } else if (blk < 2 * Mn + BFn) {
        // ---- rstats ----
        int bf = blk - 2 * Mn;
        const float* base = inp + (size_t)bf * ROWn;
        float4 mx[4];
#pragma unroll
        for (int i = 0; i < 4; i++) mx[i] = make_float4(-FLT_MAX, -FLT_MAX, -FLT_MAX, -FLT_MAX);
        for (int o = 0; o < OBJn; o++) {
            float4 x[4];
            const float4* p = (const float4*)(base + (size_t)o * Dn);
            float s = 0.f;
#pragma unroll
            for (int i = 0; i < 4; i++) {
                x[i] = p[threadIdx.x + i * 256];
                s += x[i].x * x[i].x + x[i].y * x[i].y + x[i].z * x[i].z + x[i].w * x[i].w;
            }
            s = block_reduce_sum(s);
            float inv = 1.f / fmaxf(sqrtf(s), 1e-12f);
            if (threadIdx.x == 0) g_invnorm[bf * OBJn + o] = inv;
#pragma unroll
            for (int i = 0; i < 4; i++) {
                float4 v = x[i];
                v.x *= inv; v.y *= inv; v.z *= inv; v.w *= inv;
                mx[i] = fmax4(mx[i], v);
            }
        }
        float s2 = 0.f;
#pragma unroll
        for (int i = 0; i < 4; i++)
            s2 += mx[i].x * mx[i].x + mx[i].y * mx[i].y + mx[i].z * mx[i].z + mx[i].w * mx[i].w;
        s2 = block_reduce_sum(s2);
        float inv2 = 1.f / fmaxf(sqrtf(s2), 1e-12f);
        float4* outp = (float4*)(g_rmaxn + (size_t)bf * Dn);
#pragma unroll
        for (int i = 0; i < 4; i++) {
            float4 v = mx[i];
            v.x *= inv2; v.y *= inv2; v.z *= inv2; v.w *= inv2;
            outp[threadIdx.x + i * 256] = v;
        }
    } else {
        // ---- frame selection ----
        int t = threadIdx.x;
        if (t < 16) {
            int b = t >> 2, q = t & 3;
            const float* w = qr + (b * Qn + q) * Fn;
            int hi = 0; float hv = w[0];
            for (int f = 1; f < Fn; f++) if (w[f] > hv) { hv = w[f]; hi = f; }
            int rr = rnd[b * Qn + q];
            int lo = 0;
            for (int i = 0; i < Fn; i++) {
                int rank = 0;
                for (int j = 0; j < Fn; j++)
                    rank += (w[j] < w[i]) || (w[j] == w[i] && j < i);
                if (rank == rr) { lo = i; break; }
            }
            g_high[t] = hi; g_low[t] = lo;
        }
    }
}

// ---------------- K_gemm: proven 35us FMA-floor kernel (round 3) ---------------------
__global__ __launch_bounds__(256) void k_gemm() {
    __shared__ float As[80][33];
    __shared__ float Bs[64][33];
    int tid = threadIdx.x;
    int tx = tid & 15, ty = tid >> 4;     // tx: m (16x4=64), ty: r (16x5=80)
    int m0 = blockIdx.x * 64;
    int kbase = blockIdx.y * 512;
    float acc[5][4];
#pragma unroll
    for (int i = 0; i < 5; i++)
#pragma unroll
        for (int j = 0; j < 4; j++) acc[i][j] = 0.f;

    for (int kc = 0; kc < 16; kc++) {
        int k0 = kbase + kc * 32;
        __syncthreads();
#pragma unroll
        for (int idx = tid; idx < 80 * 32; idx += 256) {
            int r = idx >> 5, kk = idx & 31;
            As[r][kk] = g_rmaxn[(size_t)r * Dn + k0 + kk];
        }
#pragma unroll
        for (int idx = tid; idx < 64 * 32; idx += 256) {
            int m = idx >> 5, kk = idx & 31;
            int mg = m0 + m;
            Bs[m][kk] = (mg < 2 * Mn) ? g_mem_mp[(size_t)mg * Dn + k0 + kk] : 0.f;
        }
        __syncthreads();
#pragma unroll
        for (int kk = 0; kk < 32; kk++) {
            float a[5], b[4];
#pragma unroll
            for (int i = 0; i < 5; i++) a[i] = As[ty * 5 + i][kk];
#pragma unroll
            for (int j = 0; j < 4; j++) b[j] = Bs[tx * 4 + j][kk];
#pragma unroll
            for (int i = 0; i < 5; i++)
#pragma unroll
                for (int j = 0; j < 4; j++) acc[i][j] = fmaf(a[i], b[j], acc[i][j]);
        }
    }
    float* dst = g_partial + (size_t)blockIdx.y * BFn * MPAD;
#pragma unroll
    for (int i = 0; i < 5; i++)
#pragma unroll
        for (int j = 0; j < 4; j++)
            dst[(ty * 5 + i) * MPAD + m0 + tx * 4 + j] = acc[i][j];
}

// ---------------- K_argmax: one block per (row, mem-half) ----------------------------
__global__ __launch_bounds__(512) void k_argmax() {
    int r = blockIdx.x >> 1;
    int h = blockIdx.x & 1;
    int tid = threadIdx.x;
    float bv = -FLT_MAX;
    int   bm = 0;
    for (int m = tid; m < Mn; m += 512) {
        int mg = h * Mn + m;
        float s = 0.f;
#pragma unroll
        for (int ks = 0; ks < KSPLIT; ks++)
            s += g_partial[(size_t)ks * BFn * MPAD + (size_t)r * MPAD + mg];
        if (s > bv || (s == bv && m < bm)) { bv = s; bm = m; }
    }
    __shared__ float sv[512];
    __shared__ int   sm2[512];
    sv[tid] = bv; sm2[tid] = bm;
    __syncthreads();
    for (int st = 256; st; st >>= 1) {
        if (tid < st) {
            float ov = sv[tid + st]; int om = sm2[tid + st];
            if (ov > sv[tid] || (ov == sv[tid] && om < sm2[tid])) {
                sv[tid] = ov; sm2[tid] = om;
            }
        }
        __syncthreads();
    }
    if (tid == 0) g_sim[h * BFn + r] = sm2[0];
}

// ---------------- K_fill: grid-stride flat work list (kills wave tail) ---------------
// 6400 items total; item = (bf, 256-float4 chunk). FILLBLKS blocks ~= 1 full wave,
// each block takes 5-6 items -> <=11% imbalance instead of a 92%-idle second wave.
__global__ __launch_bounds__(256) void k_fill(const float* __restrict__ inp,
                                              float* __restrict__ out) {
    int tid = threadIdx.x;
    float4* o4 = (float4*)out;
    const size_t rpn4 = RPN / 4;
    const int NITEM = BFn * 80;            // 6400 (80 chunks of 256 float4 per row)
    for (int it = blockIdx.x; it < NITEM; it += gridDim.x) {
        int bf = it / 80;
        int ch = it % 80;
        int b = bf / Fn, f = bf % Fn;
        int e4 = ch * 256 + tid;           // 0..20479 within the row
        int oo = e4 >> 10;                 // region (1024 float4 per region)
        float inv = g_invnorm[bf * OBJn + oo];
        float4 v = ((const float4*)(inp + (size_t)bf * ROWn))[e4];
        v.x *= inv; v.y *= inv; v.z *= inv; v.w *= inv;
#pragma unroll
        for (int q = 0; q < 4; q++) {
            int lo = g_low[b * 4 + q], hi = g_high[b * 4 + q];
            size_t ob = ((size_t)((q * Bn + b) * Fn + f)) * (ROWn / 4) + e4;
            if (f != lo) o4[ob] = v;            // Rp copy
            if (f != hi) o4[rpn4 + ob] = v;     // Rn copy
        }
    }
}

// ---------------- K_replace: replaced rows + sim outputs -----------------------------
// grid (33, 16): x<32 copy mem rows (chunk y), x==32,y==0 writes sims.
__global__ __launch_bounds__(256) void k_replace(const float* __restrict__ mem1,
                                                 const float* __restrict__ mem2,
                                                 float* __restrict__ out,
                                                 long long out_size) {
    int t = blockIdx.x;
    if (t == 32) {
        if (blockIdx.y == 0 && threadIdx.x < 16) {
            int bq = threadIdx.x;
            int b = bq >> 2, q = bq & 3;
            long long rpn2 = (long long)(2 * RPN);
            if (out_size >= rpn2 + 32) {
                out[(size_t)rpn2 + (q * Bn + b)]      =
                    (float)g_sim[BFn + b * Fn + g_high[bq]];   // high_sim
                out[(size_t)rpn2 + 16 + (q * Bn + b)] =
                    (float)g_sim[b * Fn + g_low[bq]];          // low_sim
            }
        }
        return;
    }
    int which = t & 1;         // 0: Rp/low/mem1   1: Rn/high/mem2
    int bq = t >> 1;
    int b = bq >> 2, q = bq & 3;
    int f, row;
    const float* src;
    int lo = g_low[bq];
    if (which == 0) { f = lo;         row = g_sim[b * Fn + lo];       src = mem1; }
    else            { f = g_high[bq]; row = g_sim[BFn + b * Fn + lo]; src = mem2; }
    const float4* s4 = (const float4*)(src + (size_t)row * ROWn);
    float4* d4 = (float4*)(out + (size_t)which * RPN +
                           ((size_t)((q * Bn + b) * Fn + f)) * ROWn);
    int base = blockIdx.y * 1280;          // 16 chunks of 1280 float4
#pragma unroll
    for (int i = 0; i < 5; i++) {
        int e4 = base + threadIdx.x + i * 256;
        d4[e4] = __ldcs(s4 + e4);
    }
}

// ---------------- launch ----------------
extern "C" void kernel_launch(void* const* d_in, const int* in_sizes, int n_in,
                              void* d_out, int out_size) {
    const float* qr   = (const float*)d_in[0];   // [4,4,20]
    const float* inp  = (const float*)d_in[1];   // [4,20,20,4096]
    const float* mem1 = (const float*)d_in[2];   // [1000,81920]
    const float* mem2 = (const float*)d_in[3];   // [1000,81920]
    const int*   rnd  = (const int*)d_in[4];     // [4,4,1]
    float* out = (float*)d_out;

    k_prep<<<2 * Mn + BFn + 1, 256>>>(mem1, mem2, inp, qr, rnd);
    k_gemm<<<dim3(32, KSPLIT), 256>>>();
    k_argmax<<<2 * BFn, 512>>>();
    k_fill<<<FILLBLKS, 256>>>(inp, out);
    k_replace<<<dim3(33, 16), 256>>>(mem1, mem2, out, (long long)out_size);
}